// round 1
// baseline (speedup 1.0000x reference)
#include <cuda_runtime.h>
#include <math.h>

// Problem constants (fixed by setup_inputs)
#define BATCH 2
#define SEQ   2048
#define DIM   1024
#define HEADS 16
#define DHEAD 64
#define MROWS (BATCH*SEQ)   // 4096
#define N3    (3*DIM)       // 3072
#define HALFW 64

// Scratch (static device allocations are allowed)
__device__ float g_xn[(size_t)MROWS * DIM];
__device__ float g_qkv[(size_t)MROWS * N3];
__device__ float g_att[(size_t)MROWS * DIM];

// ---------------------------------------------------------------------------
// RMSNorm: one block per row, 256 threads, float4 per thread
// ---------------------------------------------------------------------------
__global__ void rmsnorm_kernel(const float* __restrict__ x,
                               const float* __restrict__ w) {
    int row = blockIdx.x;
    const float4* xr = (const float4*)(x + (size_t)row * DIM);
    float4* o = (float4*)(g_xn + (size_t)row * DIM);
    int t = threadIdx.x;
    float4 v = xr[t];
    float ss = v.x*v.x + v.y*v.y + v.z*v.z + v.w*v.w;
    __shared__ float red[8];
    #pragma unroll
    for (int off = 16; off > 0; off >>= 1)
        ss += __shfl_xor_sync(0xffffffff, ss, off);
    if ((t & 31) == 0) red[t >> 5] = ss;
    __syncthreads();
    if (t < 32) {
        float s = (t < 8) ? red[t] : 0.0f;
        #pragma unroll
        for (int off = 4; off > 0; off >>= 1)
            s += __shfl_xor_sync(0xffffffff, s, off);
        if (t == 0) red[0] = s;
    }
    __syncthreads();
    float inv = rsqrtf(red[0] * (1.0f / DIM) + 1e-6f);
    const float4* wv4 = (const float4*)w;
    float4 wv = wv4[t];
    float4 r;
    r.x = v.x * inv * wv.x;
    r.y = v.y * inv * wv.y;
    r.z = v.z * inv * wv.z;
    r.w = v.w * inv * wv.w;
    o[t] = r;
}

// ---------------------------------------------------------------------------
// GEMM  C[M,N] = A[M,K] @ B[N,K]^T  (+ optional skip[M,N])
// BM=BN=64, BK=16, 256 threads, 4x4 per-thread microtile
// ---------------------------------------------------------------------------
#define BM 64
#define BN 64
#define BK 16

__global__ void gemm_tn_kernel(const float* __restrict__ A,
                               const float* __restrict__ B,
                               const float* __restrict__ skip,
                               float* __restrict__ C,
                               int M, int N, int K) {
    __shared__ float As[BK][BM + 4];
    __shared__ float Bs[BK][BN + 4];
    int t  = threadIdx.x;
    int tx = t & 15, ty = t >> 4;
    int m0 = blockIdx.y * BM;
    int n0 = blockIdx.x * BN;
    int lr = t >> 2;            // 0..63 tile row
    int lc = (t & 3) * 4;       // k offset 0,4,8,12
    const float* Ap = A + (size_t)(m0 + lr) * K + lc;
    const float* Bp = B + (size_t)(n0 + lr) * K + lc;

    float c[4][4] = {};
    for (int k0 = 0; k0 < K; k0 += BK) {
        float4 av = *(const float4*)(Ap + k0);
        float4 bv = *(const float4*)(Bp + k0);
        __syncthreads();
        As[lc + 0][lr] = av.x; As[lc + 1][lr] = av.y;
        As[lc + 2][lr] = av.z; As[lc + 3][lr] = av.w;
        Bs[lc + 0][lr] = bv.x; Bs[lc + 1][lr] = bv.y;
        Bs[lc + 2][lr] = bv.z; Bs[lc + 3][lr] = bv.w;
        __syncthreads();
        #pragma unroll
        for (int kk = 0; kk < BK; kk++) {
            float4 a = *(const float4*)&As[kk][ty * 4];
            float4 b = *(const float4*)&Bs[kk][tx * 4];
            float ar[4] = {a.x, a.y, a.z, a.w};
            float br[4] = {b.x, b.y, b.z, b.w};
            #pragma unroll
            for (int i = 0; i < 4; i++)
                #pragma unroll
                for (int j = 0; j < 4; j++)
                    c[i][j] += ar[i] * br[j];
        }
    }

    #pragma unroll
    for (int i = 0; i < 4; i++) {
        size_t off = (size_t)(m0 + ty * 4 + i) * N + n0 + tx * 4;
        float4 r = make_float4(c[i][0], c[i][1], c[i][2], c[i][3]);
        if (skip) {
            float4 s = *(const float4*)(skip + off);
            r.x += s.x; r.y += s.y; r.z += s.z; r.w += s.w;
        }
        *(float4*)(C + off) = r;
    }
}

// ---------------------------------------------------------------------------
// Banded attention: one block per (b, h, 32-query tile)
// Keys span [q0-64, q0+31+64] -> 160 slots. Q/K/V/S staged in dynamic smem.
// K/V rows padded to stride 68 to avoid 32-way LDS bank conflicts.
// ---------------------------------------------------------------------------
#define TQ   32
#define SPAN 160
#define KVST 68   // padded row stride for K/V tiles

__global__ void attn_kernel() {
    extern __shared__ float sm[];
    float* Qs = sm;                      // TQ * DHEAD
    float* Ks = Qs + TQ * DHEAD;         // SPAN * KVST
    float* Vs = Ks + SPAN * KVST;        // SPAN * KVST
    float* Ss = Vs + SPAN * KVST;        // TQ * SPAN

    int t  = threadIdx.x;
    int bh = blockIdx.y;
    int b  = bh >> 4, h = bh & 15;
    int q0 = blockIdx.x * TQ;
    int kstart = q0 - HALFW;
    size_t base = (size_t)(b * SEQ) * N3;

    // load Q tile
    for (int idx = t; idx < TQ * (DHEAD / 4); idx += 256) {
        int i  = idx / (DHEAD / 4);
        int d4 = idx % (DHEAD / 4);
        float4 v = *(const float4*)&g_qkv[base + (size_t)(q0 + i) * N3 + h * DHEAD + d4 * 4];
        *(float4*)&Qs[i * DHEAD + d4 * 4] = v;
    }
    // load K and V tiles (zero-fill out-of-range)
    for (int idx = t; idx < SPAN * (DHEAD / 4); idx += 256) {
        int jj = idx / (DHEAD / 4);
        int d4 = idx % (DHEAD / 4);
        int j  = kstart + jj;
        float4 kv = make_float4(0, 0, 0, 0), vv = kv;
        if (j >= 0 && j < SEQ) {
            kv = *(const float4*)&g_qkv[base + (size_t)j * N3 + DIM     + h * DHEAD + d4 * 4];
            vv = *(const float4*)&g_qkv[base + (size_t)j * N3 + 2 * DIM + h * DHEAD + d4 * 4];
        }
        *(float4*)&Ks[jj * KVST + d4 * 4] = kv;
        *(float4*)&Vs[jj * KVST + d4 * 4] = vv;
    }
    __syncthreads();

    // scores S[i][jj] = (Q_i . K_jj) / 8, band-masked
    const float scale = 0.125f;
    for (int o = t; o < TQ * SPAN; o += 256) {
        int i  = o / SPAN;
        int jj = o % SPAN;
        int j  = kstart + jj;
        int di = (q0 + i) - j; if (di < 0) di = -di;
        float s;
        if (j < 0 || j >= SEQ || di > HALFW) {
            s = -1e30f;
        } else {
            const float4* qa = (const float4*)&Qs[i * DHEAD];
            const float4* ka = (const float4*)&Ks[jj * KVST];
            float acc = 0.0f;
            #pragma unroll
            for (int d = 0; d < DHEAD / 4; d++) {
                float4 a = qa[d], kb = ka[d];
                acc += a.x * kb.x + a.y * kb.y + a.z * kb.z + a.w * kb.w;
            }
            s = acc * scale;
        }
        Ss[o] = s;
    }
    __syncthreads();

    // softmax: warp w handles rows 4w..4w+3, 5 cols per lane (160 = 32*5)
    int w = t >> 5, lane = t & 31;
    #pragma unroll
    for (int r = 0; r < 4; r++) {
        int i = w * 4 + r;
        float vals[5];
        float vmax = -1e30f;
        #pragma unroll
        for (int c = 0; c < 5; c++) {
            vals[c] = Ss[i * SPAN + lane + 32 * c];
            vmax = fmaxf(vmax, vals[c]);
        }
        #pragma unroll
        for (int off = 16; off > 0; off >>= 1)
            vmax = fmaxf(vmax, __shfl_xor_sync(0xffffffff, vmax, off));
        float sum = 0.0f;
        #pragma unroll
        for (int c = 0; c < 5; c++) {
            vals[c] = __expf(vals[c] - vmax);
            sum += vals[c];
        }
        #pragma unroll
        for (int off = 16; off > 0; off >>= 1)
            sum += __shfl_xor_sync(0xffffffff, sum, off);
        float inv = 1.0f / sum;
        #pragma unroll
        for (int c = 0; c < 5; c++)
            Ss[i * SPAN + lane + 32 * c] = vals[c] * inv;
    }
    __syncthreads();

    // O = P V : thread computes row i = t/8, dims (t%8)*8 .. +7
    int i  = t >> 3;
    int d0 = (t & 7) * 8;
    float acc[8] = {};
    for (int jj = 0; jj < SPAN; jj++) {
        float p = Ss[i * SPAN + jj];
        const float* vrow = &Vs[jj * KVST + d0];
        #pragma unroll
        for (int d = 0; d < 8; d++) acc[d] += p * vrow[d];
    }
    float* orow = &g_att[(size_t)(b * SEQ + q0 + i) * DIM + h * DHEAD + d0];
    *(float4*)orow       = make_float4(acc[0], acc[1], acc[2], acc[3]);
    *(float4*)(orow + 4) = make_float4(acc[4], acc[5], acc[6], acc[7]);
}

// ---------------------------------------------------------------------------
// launch
// ---------------------------------------------------------------------------
extern "C" void kernel_launch(void* const* d_in, const int* in_sizes, int n_in,
                              void* d_out, int out_size) {
    const float* x      = (const float*)d_in[0];
    const float* w_norm = (const float*)d_in[1];
    const float* w_qkv  = (const float*)d_in[2];
    const float* w_out  = (const float*)d_in[3];
    float* out = (float*)d_out;

    float *p_xn, *p_qkv, *p_att;
    cudaGetSymbolAddress((void**)&p_xn,  g_xn);
    cudaGetSymbolAddress((void**)&p_qkv, g_qkv);
    cudaGetSymbolAddress((void**)&p_att, g_att);

    // attention smem: Q(32*64) + K(160*68) + V(160*68) + S(32*160) floats
    size_t attn_smem = (size_t)(TQ * DHEAD + 2 * SPAN * KVST + TQ * SPAN) * sizeof(float);
    cudaFuncSetAttribute(attn_kernel, cudaFuncAttributeMaxDynamicSharedMemorySize,
                         (int)attn_smem);

    // 1. RMSNorm
    rmsnorm_kernel<<<MROWS, 256>>>(x, w_norm);

    // 2. QKV projection: g_qkv[M, 3D] = g_xn @ w_qkv^T
    {
        dim3 grid(N3 / BN, MROWS / BM);
        gemm_tn_kernel<<<grid, 256>>>(p_xn, w_qkv, nullptr, p_qkv, MROWS, N3, DIM);
    }

    // 3. Banded attention -> g_att[M, D]
    {
        dim3 grid(SEQ / TQ, BATCH * HEADS);
        attn_kernel<<<grid, 256, attn_smem>>>();
    }

    // 4. Output projection + residual: out = g_att @ w_out^T + x
    {
        dim3 grid(DIM / BN, MROWS / BM);
        gemm_tn_kernel<<<grid, 256>>>(p_att, w_out, x, out, MROWS, DIM, DIM);
    }
}

// round 2
// speedup vs baseline: 1.9190x; 1.9190x over previous
#include <cuda_runtime.h>
#include <math.h>

// Problem constants (fixed by setup_inputs)
#define BATCH 2
#define SEQ   2048
#define DIM   1024
#define HEADS 16
#define DHEAD 64
#define MROWS (BATCH*SEQ)   // 4096
#define N3    (3*DIM)       // 3072
#define HALFW 64

// Scratch (static device allocations are allowed)
__device__ float g_xn[(size_t)MROWS * DIM];
__device__ float g_qkv[(size_t)MROWS * N3];
__device__ float g_att[(size_t)MROWS * DIM];

// ---------------------------------------------------------------------------
// RMSNorm: one block per row, 256 threads, float4 per thread
// ---------------------------------------------------------------------------
__global__ void rmsnorm_kernel(const float* __restrict__ x,
                               const float* __restrict__ w) {
    int row = blockIdx.x;
    const float4* xr = (const float4*)(x + (size_t)row * DIM);
    float4* o = (float4*)(g_xn + (size_t)row * DIM);
    int t = threadIdx.x;
    float4 v = xr[t];
    float ss = v.x*v.x + v.y*v.y + v.z*v.z + v.w*v.w;
    __shared__ float red[8];
    #pragma unroll
    for (int off = 16; off > 0; off >>= 1)
        ss += __shfl_xor_sync(0xffffffff, ss, off);
    if ((t & 31) == 0) red[t >> 5] = ss;
    __syncthreads();
    if (t < 32) {
        float s = (t < 8) ? red[t] : 0.0f;
        #pragma unroll
        for (int off = 4; off > 0; off >>= 1)
            s += __shfl_xor_sync(0xffffffff, s, off);
        if (t == 0) red[0] = s;
    }
    __syncthreads();
    float inv = rsqrtf(red[0] * (1.0f / DIM) + 1e-6f);
    const float4* wv4 = (const float4*)w;
    float4 wv = wv4[t];
    float4 r;
    r.x = v.x * inv * wv.x;
    r.y = v.y * inv * wv.y;
    r.z = v.z * inv * wv.z;
    r.w = v.w * inv * wv.w;
    o[t] = r;
}

// ---------------------------------------------------------------------------
// TF32 tensor-core GEMM:  C[M,N] = A[M,K] @ B[N,K]^T  (+ optional skip)
// CTA tile 128x128x16, 8 warps, warp tile 32x64, mma.sync.m16n8k8.tf32
// smem layout: [row][k] with stride 20 floats -> conflict-free fragment loads
// Register-prefetch double buffering, 1 syncthreads per K-step.
// ---------------------------------------------------------------------------
#define GBM 128
#define GBN 128
#define GBK 16
#define KST 20   // GBK + 4 pad; (20*gid + tig) mod 32 hits all banks

__device__ __forceinline__ unsigned f2tf32(float x) {
    unsigned r;
    asm("cvt.rna.tf32.f32 %0, %1;" : "=r"(r) : "f"(x));
    return r;
}

__device__ __forceinline__ void mma_tf32(float c[4],
                                         const unsigned a[4],
                                         const unsigned b[2]) {
    asm volatile(
        "mma.sync.aligned.m16n8k8.row.col.f32.tf32.tf32.f32 "
        "{%0,%1,%2,%3}, {%4,%5,%6,%7}, {%8,%9}, {%0,%1,%2,%3};"
        : "+f"(c[0]), "+f"(c[1]), "+f"(c[2]), "+f"(c[3])
        : "r"(a[0]), "r"(a[1]), "r"(a[2]), "r"(a[3]),
          "r"(b[0]), "r"(b[1]));
}

__global__ __launch_bounds__(256, 2)
void gemm_tf32_kernel(const float* __restrict__ A,
                      const float* __restrict__ B,
                      const float* __restrict__ skip,
                      float* __restrict__ C,
                      int M, int N, int K) {
    __shared__ unsigned As[2][GBM * KST];
    __shared__ unsigned Bs[2][GBN * KST];

    int t    = threadIdx.x;
    int lane = t & 31;
    int wid  = t >> 5;
    int wm   = (wid >> 1) * 32;   // warp m-offset within CTA tile (4 warps)
    int wn   = (wid & 1) * 64;    // warp n-offset (2 warps)
    int gid  = lane >> 2;         // 0..7
    int tig  = lane & 3;          // 0..3
    int m0   = blockIdx.y * GBM;
    int n0   = blockIdx.x * GBN;

    // Each thread loads 8 consecutive k for one row per tile.
    int ldrow = t >> 1;           // 0..127
    int ldk   = (t & 1) * 8;      // 0 or 8
    const float* Ap = A + (size_t)(m0 + ldrow) * K + ldk;
    const float* Bp = B + (size_t)(n0 + ldrow) * K + ldk;
    unsigned* sAdst = &As[0][ldrow * KST + ldk];  // buffer offset added later
    unsigned* sBdst = &Bs[0][ldrow * KST + ldk];
    const int bufstride = GBM * KST;              // same for As/Bs (GBM==GBN)

    float acc[2][8][4] = {};

    int nk = K / GBK;

    // prologue: tile 0 -> buf 0
    {
        float4 a0 = *(const float4*)(Ap);
        float4 a1 = *(const float4*)(Ap + 4);
        float4 b0 = *(const float4*)(Bp);
        float4 b1 = *(const float4*)(Bp + 4);
        uint4 ua0 = make_uint4(f2tf32(a0.x), f2tf32(a0.y), f2tf32(a0.z), f2tf32(a0.w));
        uint4 ua1 = make_uint4(f2tf32(a1.x), f2tf32(a1.y), f2tf32(a1.z), f2tf32(a1.w));
        uint4 ub0 = make_uint4(f2tf32(b0.x), f2tf32(b0.y), f2tf32(b0.z), f2tf32(b0.w));
        uint4 ub1 = make_uint4(f2tf32(b1.x), f2tf32(b1.y), f2tf32(b1.z), f2tf32(b1.w));
        *(uint4*)(sAdst)     = ua0;
        *(uint4*)(sAdst + 4) = ua1;
        *(uint4*)(sBdst)     = ub0;
        *(uint4*)(sBdst + 4) = ub1;
    }
    __syncthreads();

    for (int kt = 0; kt < nk; kt++) {
        int buf = kt & 1;

        // prefetch next tile into registers
        float4 pa0, pa1, pb0, pb1;
        if (kt + 1 < nk) {
            const float* Apn = Ap + (kt + 1) * GBK;
            const float* Bpn = Bp + (kt + 1) * GBK;
            pa0 = *(const float4*)(Apn);
            pa1 = *(const float4*)(Apn + 4);
            pb0 = *(const float4*)(Bpn);
            pb1 = *(const float4*)(Bpn + 4);
        }

        // compute: two k8 steps
        const unsigned* sA = &As[0][buf * bufstride];
        const unsigned* sB = &Bs[0][buf * bufstride];
        #pragma unroll
        for (int kk = 0; kk < 2; kk++) {
            int kb = kk * 8;
            unsigned afr[2][4];
            #pragma unroll
            for (int mi = 0; mi < 2; mi++) {
                int mr = wm + mi * 16 + gid;
                afr[mi][0] = sA[mr * KST + kb + tig];
                afr[mi][1] = sA[(mr + 8) * KST + kb + tig];
                afr[mi][2] = sA[mr * KST + kb + tig + 4];
                afr[mi][3] = sA[(mr + 8) * KST + kb + tig + 4];
            }
            #pragma unroll
            for (int ni = 0; ni < 8; ni++) {
                unsigned bfr[2];
                int nr = wn + ni * 8 + gid;
                bfr[0] = sB[nr * KST + kb + tig];
                bfr[1] = sB[nr * KST + kb + tig + 4];
                mma_tf32(acc[0][ni], afr[0], bfr);
                mma_tf32(acc[1][ni], afr[1], bfr);
            }
        }

        if (kt + 1 < nk) {
            int nb = (kt + 1) & 1;
            unsigned* dA = sAdst + nb * bufstride;
            unsigned* dB = sBdst + nb * bufstride;
            *(uint4*)(dA)     = make_uint4(f2tf32(pa0.x), f2tf32(pa0.y), f2tf32(pa0.z), f2tf32(pa0.w));
            *(uint4*)(dA + 4) = make_uint4(f2tf32(pa1.x), f2tf32(pa1.y), f2tf32(pa1.z), f2tf32(pa1.w));
            *(uint4*)(dB)     = make_uint4(f2tf32(pb0.x), f2tf32(pb0.y), f2tf32(pb0.z), f2tf32(pb0.w));
            *(uint4*)(dB + 4) = make_uint4(f2tf32(pb1.x), f2tf32(pb1.y), f2tf32(pb1.z), f2tf32(pb1.w));
            __syncthreads();
        }
    }

    // epilogue
    #pragma unroll
    for (int mi = 0; mi < 2; mi++) {
        #pragma unroll
        for (int ni = 0; ni < 8; ni++) {
            int r0  = m0 + wm + mi * 16 + gid;
            int col = n0 + wn + ni * 8 + tig * 2;
            float2 v0 = make_float2(acc[mi][ni][0], acc[mi][ni][1]);
            float2 v1 = make_float2(acc[mi][ni][2], acc[mi][ni][3]);
            size_t o0 = (size_t)r0 * N + col;
            size_t o1 = (size_t)(r0 + 8) * N + col;
            if (skip) {
                float2 s0 = *(const float2*)(skip + o0);
                float2 s1 = *(const float2*)(skip + o1);
                v0.x += s0.x; v0.y += s0.y;
                v1.x += s1.x; v1.y += s1.y;
            }
            *(float2*)(C + o0) = v0;
            *(float2*)(C + o1) = v1;
        }
    }
}

// ---------------------------------------------------------------------------
// Banded attention: one block per (b, h, 32-query tile)
// ---------------------------------------------------------------------------
#define TQ   32
#define SPAN 160
#define KVST 68   // padded row stride for K/V tiles

__global__ void attn_kernel() {
    extern __shared__ float sm[];
    float* Qs = sm;                      // TQ * DHEAD
    float* Ks = Qs + TQ * DHEAD;         // SPAN * KVST
    float* Vs = Ks + SPAN * KVST;        // SPAN * KVST
    float* Ss = Vs + SPAN * KVST;        // TQ * SPAN

    int t  = threadIdx.x;
    int bh = blockIdx.y;
    int b  = bh >> 4, h = bh & 15;
    int q0 = blockIdx.x * TQ;
    int kstart = q0 - HALFW;
    size_t base = (size_t)(b * SEQ) * N3;

    for (int idx = t; idx < TQ * (DHEAD / 4); idx += 256) {
        int i  = idx / (DHEAD / 4);
        int d4 = idx % (DHEAD / 4);
        float4 v = *(const float4*)&g_qkv[base + (size_t)(q0 + i) * N3 + h * DHEAD + d4 * 4];
        *(float4*)&Qs[i * DHEAD + d4 * 4] = v;
    }
    for (int idx = t; idx < SPAN * (DHEAD / 4); idx += 256) {
        int jj = idx / (DHEAD / 4);
        int d4 = idx % (DHEAD / 4);
        int j  = kstart + jj;
        float4 kv = make_float4(0, 0, 0, 0), vv = kv;
        if (j >= 0 && j < SEQ) {
            kv = *(const float4*)&g_qkv[base + (size_t)j * N3 + DIM     + h * DHEAD + d4 * 4];
            vv = *(const float4*)&g_qkv[base + (size_t)j * N3 + 2 * DIM + h * DHEAD + d4 * 4];
        }
        *(float4*)&Ks[jj * KVST + d4 * 4] = kv;
        *(float4*)&Vs[jj * KVST + d4 * 4] = vv;
    }
    __syncthreads();

    const float scale = 0.125f;
    for (int o = t; o < TQ * SPAN; o += 256) {
        int i  = o / SPAN;
        int jj = o % SPAN;
        int j  = kstart + jj;
        int di = (q0 + i) - j; if (di < 0) di = -di;
        float s;
        if (j < 0 || j >= SEQ || di > HALFW) {
            s = -1e30f;
        } else {
            const float4* qa = (const float4*)&Qs[i * DHEAD];
            const float4* ka = (const float4*)&Ks[jj * KVST];
            float acc = 0.0f;
            #pragma unroll
            for (int d = 0; d < DHEAD / 4; d++) {
                float4 a = qa[d], kb = ka[d];
                acc += a.x * kb.x + a.y * kb.y + a.z * kb.z + a.w * kb.w;
            }
            s = acc * scale;
        }
        Ss[o] = s;
    }
    __syncthreads();

    int w = t >> 5, lane = t & 31;
    #pragma unroll
    for (int r = 0; r < 4; r++) {
        int i = w * 4 + r;
        float vals[5];
        float vmax = -1e30f;
        #pragma unroll
        for (int c = 0; c < 5; c++) {
            vals[c] = Ss[i * SPAN + lane + 32 * c];
            vmax = fmaxf(vmax, vals[c]);
        }
        #pragma unroll
        for (int off = 16; off > 0; off >>= 1)
            vmax = fmaxf(vmax, __shfl_xor_sync(0xffffffff, vmax, off));
        float sum = 0.0f;
        #pragma unroll
        for (int c = 0; c < 5; c++) {
            vals[c] = __expf(vals[c] - vmax);
            sum += vals[c];
        }
        #pragma unroll
        for (int off = 16; off > 0; off >>= 1)
            sum += __shfl_xor_sync(0xffffffff, sum, off);
        float inv = 1.0f / sum;
        #pragma unroll
        for (int c = 0; c < 5; c++)
            Ss[i * SPAN + lane + 32 * c] = vals[c] * inv;
    }
    __syncthreads();

    int i  = t >> 3;
    int d0 = (t & 7) * 8;
    float acc[8] = {};
    for (int jj = 0; jj < SPAN; jj++) {
        float p = Ss[i * SPAN + jj];
        const float* vrow = &Vs[jj * KVST + d0];
        #pragma unroll
        for (int d = 0; d < 8; d++) acc[d] += p * vrow[d];
    }
    float* orow = &g_att[(size_t)(b * SEQ + q0 + i) * DIM + h * DHEAD + d0];
    *(float4*)orow       = make_float4(acc[0], acc[1], acc[2], acc[3]);
    *(float4*)(orow + 4) = make_float4(acc[4], acc[5], acc[6], acc[7]);
}

// ---------------------------------------------------------------------------
// launch
// ---------------------------------------------------------------------------
extern "C" void kernel_launch(void* const* d_in, const int* in_sizes, int n_in,
                              void* d_out, int out_size) {
    const float* x      = (const float*)d_in[0];
    const float* w_norm = (const float*)d_in[1];
    const float* w_qkv  = (const float*)d_in[2];
    const float* w_out  = (const float*)d_in[3];
    float* out = (float*)d_out;

    float *p_xn, *p_qkv, *p_att;
    cudaGetSymbolAddress((void**)&p_xn,  g_xn);
    cudaGetSymbolAddress((void**)&p_qkv, g_qkv);
    cudaGetSymbolAddress((void**)&p_att, g_att);

    size_t attn_smem = (size_t)(TQ * DHEAD + 2 * SPAN * KVST + TQ * SPAN) * sizeof(float);
    cudaFuncSetAttribute(attn_kernel, cudaFuncAttributeMaxDynamicSharedMemorySize,
                         (int)attn_smem);

    // 1. RMSNorm
    rmsnorm_kernel<<<MROWS, 256>>>(x, w_norm);

    // 2. QKV projection: g_qkv[M, 3D] = g_xn @ w_qkv^T   (TF32 tensor cores)
    {
        dim3 grid(N3 / GBN, MROWS / GBM);
        gemm_tf32_kernel<<<grid, 256>>>(p_xn, w_qkv, nullptr, p_qkv, MROWS, N3, DIM);
    }

    // 3. Banded attention -> g_att[M, D]
    {
        dim3 grid(SEQ / TQ, BATCH * HEADS);
        attn_kernel<<<grid, 256, attn_smem>>>();
    }

    // 4. Output projection + residual: out = g_att @ w_out^T + x
    {
        dim3 grid(DIM / GBN, MROWS / GBM);
        gemm_tf32_kernel<<<grid, 256>>>(p_att, w_out, x, out, MROWS, DIM, DIM);
    }
}

// round 4
// speedup vs baseline: 3.0483x; 1.5885x over previous
#include <cuda_runtime.h>
#include <math.h>

// Problem constants (fixed by setup_inputs)
#define BATCH 2
#define SEQ   2048
#define DIM   1024
#define HEADS 16
#define DHEAD 64
#define MROWS (BATCH*SEQ)   // 4096
#define N3    (3*DIM)       // 3072
#define HALFW 64

// Scratch
__device__ float g_xn[(size_t)MROWS * DIM];
__device__ float g_qkv[(size_t)MROWS * N3];
__device__ float g_att[(size_t)MROWS * DIM];

// ---------------------------------------------------------------------------
// helpers
// ---------------------------------------------------------------------------
__device__ __forceinline__ unsigned f2tf32(float x) {
    unsigned r;
    asm("cvt.rna.tf32.f32 %0, %1;" : "=r"(r) : "f"(x));
    return r;
}

__device__ __forceinline__ void mma_tf32(float c[4],
                                         const unsigned a[4],
                                         const unsigned b[2]) {
    asm volatile(
        "mma.sync.aligned.m16n8k8.row.col.f32.tf32.tf32.f32 "
        "{%0,%1,%2,%3}, {%4,%5,%6,%7}, {%8,%9}, {%0,%1,%2,%3};"
        : "+f"(c[0]), "+f"(c[1]), "+f"(c[2]), "+f"(c[3])
        : "r"(a[0]), "r"(a[1]), "r"(a[2]), "r"(a[3]),
          "r"(b[0]), "r"(b[1]));
}

__device__ __forceinline__ void cp16(unsigned saddr, const void* g) {
    asm volatile("cp.async.cg.shared.global [%0], [%1], 16;\n"
                 :: "r"(saddr), "l"(g));
}
__device__ __forceinline__ void cp_commit() {
    asm volatile("cp.async.commit_group;\n" ::: "memory");
}
template <int N>
__device__ __forceinline__ void cp_wait() {
    asm volatile("cp.async.wait_group %0;\n" :: "n"(N) : "memory");
}

// ---------------------------------------------------------------------------
// RMSNorm: one block per row, 256 threads, float4 per thread
// ---------------------------------------------------------------------------
__global__ void rmsnorm_kernel(const float* __restrict__ x,
                               const float* __restrict__ w) {
    int row = blockIdx.x;
    const float4* xr = (const float4*)(x + (size_t)row * DIM);
    float4* o = (float4*)(g_xn + (size_t)row * DIM);
    int t = threadIdx.x;
    float4 v = xr[t];
    float ss = v.x*v.x + v.y*v.y + v.z*v.z + v.w*v.w;
    __shared__ float red[8];
    #pragma unroll
    for (int off = 16; off > 0; off >>= 1)
        ss += __shfl_xor_sync(0xffffffff, ss, off);
    if ((t & 31) == 0) red[t >> 5] = ss;
    __syncthreads();
    if (t < 32) {
        float s = (t < 8) ? red[t] : 0.0f;
        #pragma unroll
        for (int off = 4; off > 0; off >>= 1)
            s += __shfl_xor_sync(0xffffffff, s, off);
        if (t == 0) red[0] = s;
    }
    __syncthreads();
    float inv = rsqrtf(red[0] * (1.0f / DIM) + 1e-6f);
    const float4* wv4 = (const float4*)w;
    float4 wv = wv4[t];
    float4 r;
    r.x = v.x * inv * wv.x;
    r.y = v.y * inv * wv.y;
    r.z = v.z * inv * wv.z;
    r.w = v.w * inv * wv.w;
    o[t] = r;
}

// ---------------------------------------------------------------------------
// TF32 tensor-core GEMM:  C[M,N] = A[M,K] @ B[N,K]^T  (+ optional skip)
// CTA tile 128x128x16, 8 warps, warp tile 32x64, mma.sync.m16n8k8.tf32
// 4-stage cp.async pipeline in DYNAMIC smem (80KB). Raw fp32 bits as tf32.
// ---------------------------------------------------------------------------
#define GBM 128
#define GBN 128
#define GBK 16
#define KST 20   // GBK + 4 pad -> conflict-free fragment loads
#define STAGES 4
#define GEMM_SMEM (STAGES * 2 * GBM * KST * sizeof(float))   // 81920 bytes

__global__ __launch_bounds__(256, 2)
void gemm_tf32_kernel(const float* __restrict__ A,
                      const float* __restrict__ B,
                      const float* __restrict__ skip,
                      float* __restrict__ C,
                      int M, int N, int K) {
    extern __shared__ float smg[];
    float* As = smg;                         // STAGES * GBM * KST
    float* Bs = smg + STAGES * GBM * KST;    // STAGES * GBN * KST

    int t    = threadIdx.x;
    int lane = t & 31;
    int wid  = t >> 5;
    int wm   = (wid >> 1) * 32;
    int wn   = (wid & 1) * 64;
    int gid  = lane >> 2;
    int tig  = lane & 3;
    int m0   = blockIdx.y * GBM;
    int n0   = blockIdx.x * GBN;

    int ldrow = t >> 1;           // 0..127
    int ldk   = (t & 1) * 8;      // 0 or 8
    const float* Ap = A + (size_t)(m0 + ldrow) * K + ldk;
    const float* Bp = B + (size_t)(n0 + ldrow) * K + ldk;
    unsigned sAbase = (unsigned)__cvta_generic_to_shared(&As[ldrow * KST + ldk]);
    unsigned sBbase = (unsigned)__cvta_generic_to_shared(&Bs[ldrow * KST + ldk]);
    const unsigned stagebytes = GBM * KST * sizeof(float);

    float acc[2][8][4] = {};
    int nk = K / GBK;

    // prologue: issue tiles 0..STAGES-2
    #pragma unroll
    for (int s = 0; s < STAGES - 1; s++) {
        cp16(sAbase + s * stagebytes, Ap + s * GBK);
        cp16(sAbase + s * stagebytes + 16, Ap + s * GBK + 4);
        cp16(sBbase + s * stagebytes, Bp + s * GBK);
        cp16(sBbase + s * stagebytes + 16, Bp + s * GBK + 4);
        cp_commit();
    }

    for (int kt = 0; kt < nk; kt++) {
        cp_wait<STAGES - 2>();
        __syncthreads();

        if (kt + STAGES - 1 < nk) {
            int s = (kt + STAGES - 1) & (STAGES - 1);
            cp16(sAbase + s * stagebytes, Ap + (kt + STAGES - 1) * GBK);
            cp16(sAbase + s * stagebytes + 16, Ap + (kt + STAGES - 1) * GBK + 4);
            cp16(sBbase + s * stagebytes, Bp + (kt + STAGES - 1) * GBK);
            cp16(sBbase + s * stagebytes + 16, Bp + (kt + STAGES - 1) * GBK + 4);
        }
        cp_commit();

        const float* sA = &As[(kt & (STAGES - 1)) * GBM * KST];
        const float* sB = &Bs[(kt & (STAGES - 1)) * GBN * KST];
        #pragma unroll
        for (int kk = 0; kk < 2; kk++) {
            int kb = kk * 8;
            unsigned afr[2][4];
            #pragma unroll
            for (int mi = 0; mi < 2; mi++) {
                int mr = wm + mi * 16 + gid;
                afr[mi][0] = __float_as_uint(sA[mr * KST + kb + tig]);
                afr[mi][1] = __float_as_uint(sA[(mr + 8) * KST + kb + tig]);
                afr[mi][2] = __float_as_uint(sA[mr * KST + kb + tig + 4]);
                afr[mi][3] = __float_as_uint(sA[(mr + 8) * KST + kb + tig + 4]);
            }
            #pragma unroll
            for (int ni = 0; ni < 8; ni++) {
                unsigned bfr[2];
                int nr = wn + ni * 8 + gid;
                bfr[0] = __float_as_uint(sB[nr * KST + kb + tig]);
                bfr[1] = __float_as_uint(sB[nr * KST + kb + tig + 4]);
                mma_tf32(acc[0][ni], afr[0], bfr);
                mma_tf32(acc[1][ni], afr[1], bfr);
            }
        }
    }

    // epilogue
    #pragma unroll
    for (int mi = 0; mi < 2; mi++) {
        #pragma unroll
        for (int ni = 0; ni < 8; ni++) {
            int r0  = m0 + wm + mi * 16 + gid;
            int col = n0 + wn + ni * 8 + tig * 2;
            float2 v0 = make_float2(acc[mi][ni][0], acc[mi][ni][1]);
            float2 v1 = make_float2(acc[mi][ni][2], acc[mi][ni][3]);
            size_t o0 = (size_t)r0 * N + col;
            size_t o1 = (size_t)(r0 + 8) * N + col;
            if (skip) {
                float2 s0 = *(const float2*)(skip + o0);
                float2 s1 = *(const float2*)(skip + o1);
                v0.x += s0.x; v0.y += s0.y;
                v1.x += s1.x; v1.y += s1.y;
            }
            *(float2*)(C + o0) = v0;
            *(float2*)(C + o1) = v1;
        }
    }
}

// ---------------------------------------------------------------------------
// Banded attention with tensor cores.
// One block per (b, h, 32-query tile). S = QK^T and O = PV via tf32 mma.
// ---------------------------------------------------------------------------
#define TQ   32
#define SPAN 160
#define QST  68     // Q row stride (k=64 + 4)
#define KSTR 68     // K row stride
#define VTST 165    // Vt row stride over jj (160 + 5)
#define SST  165    // S row stride over jj

__global__ __launch_bounds__(256) void attn_kernel() {
    extern __shared__ float sm[];
    float* Qs = sm;                       // TQ * QST
    float* Ks = Qs + TQ * QST;            // SPAN * KSTR
    float* Vt = Ks + SPAN * KSTR;         // DHEAD * VTST (transposed V)
    float* Ss = Vt + DHEAD * VTST;        // TQ * SST

    int t    = threadIdx.x;
    int lane = t & 31;
    int w    = t >> 5;
    int gid  = lane >> 2;
    int tig  = lane & 3;
    int bh = blockIdx.y;
    int b  = bh >> 4, h = bh & 15;
    int q0 = blockIdx.x * TQ;
    int kstart = q0 - HALFW;
    size_t base = (size_t)(b * SEQ) * N3;

    // load Q (32 rows x 16 float4)
    for (int idx = t; idx < TQ * 16; idx += 256) {
        int i  = idx >> 4;
        int d4 = idx & 15;
        float4 v = *(const float4*)&g_qkv[base + (size_t)(q0 + i) * N3 + h * DHEAD + d4 * 4];
        float* dst = &Qs[i * QST + d4 * 4];
        dst[0] = __uint_as_float(f2tf32(v.x));
        dst[1] = __uint_as_float(f2tf32(v.y));
        dst[2] = __uint_as_float(f2tf32(v.z));
        dst[3] = __uint_as_float(f2tf32(v.w));
    }
    // load K rows + V transposed (zero-fill out-of-range)
    for (int idx = t; idx < SPAN * 16; idx += 256) {
        int jj = idx >> 4;
        int d4 = idx & 15;
        int j  = kstart + jj;
        float4 kv = make_float4(0, 0, 0, 0), vv = kv;
        if (j >= 0 && j < SEQ) {
            kv = *(const float4*)&g_qkv[base + (size_t)j * N3 + DIM     + h * DHEAD + d4 * 4];
            vv = *(const float4*)&g_qkv[base + (size_t)j * N3 + 2 * DIM + h * DHEAD + d4 * 4];
        }
        float* kd = &Ks[jj * KSTR + d4 * 4];
        kd[0] = __uint_as_float(f2tf32(kv.x));
        kd[1] = __uint_as_float(f2tf32(kv.y));
        kd[2] = __uint_as_float(f2tf32(kv.z));
        kd[3] = __uint_as_float(f2tf32(kv.w));
        int d0 = d4 * 4;
        Vt[(d0 + 0) * VTST + jj] = __uint_as_float(f2tf32(vv.x));
        Vt[(d0 + 1) * VTST + jj] = __uint_as_float(f2tf32(vv.y));
        Vt[(d0 + 2) * VTST + jj] = __uint_as_float(f2tf32(vv.z));
        Vt[(d0 + 3) * VTST + jj] = __uint_as_float(f2tf32(vv.w));
    }
    __syncthreads();

    // S = Q K^T / 8, band-masked. Warp w: m-tile (w&1), n-tiles (w>>1)*5..+4
    {
        int mt = w & 1;
        int ng = w >> 1;
        unsigned afr[8][4];
        #pragma unroll
        for (int kk = 0; kk < 8; kk++) {
            int mr = mt * 16 + gid;
            int kb = kk * 8;
            afr[kk][0] = __float_as_uint(Qs[mr * QST + kb + tig]);
            afr[kk][1] = __float_as_uint(Qs[(mr + 8) * QST + kb + tig]);
            afr[kk][2] = __float_as_uint(Qs[mr * QST + kb + tig + 4]);
            afr[kk][3] = __float_as_uint(Qs[(mr + 8) * QST + kb + tig + 4]);
        }
        #pragma unroll
        for (int l = 0; l < 5; l++) {
            int nt = ng * 5 + l;
            int nr = nt * 8 + gid;
            float acc[4] = {0.f, 0.f, 0.f, 0.f};
            #pragma unroll
            for (int kk = 0; kk < 8; kk++) {
                unsigned bfr[2];
                bfr[0] = __float_as_uint(Ks[nr * KSTR + kk * 8 + tig]);
                bfr[1] = __float_as_uint(Ks[nr * KSTR + kk * 8 + tig + 4]);
                mma_tf32(acc, afr[kk], bfr);
            }
            // masked store (scale 1/8)
            int i0  = mt * 16 + gid;
            int col = nt * 8 + tig * 2;
            #pragma unroll
            for (int rr = 0; rr < 2; rr++) {
                int i = i0 + rr * 8;
                int qi = q0 + i;
                #pragma unroll
                for (int c = 0; c < 2; c++) {
                    int jj = col + c;
                    int j  = kstart + jj;
                    int di = qi - j; if (di < 0) di = -di;
                    bool valid = (j >= 0) && (j < SEQ) && (di <= HALFW);
                    Ss[i * SST + jj] = valid ? acc[rr * 2 + c] * 0.125f : -1e30f;
                }
            }
        }
    }
    __syncthreads();

    // softmax: warp w handles rows 4w..4w+3, 5 cols per lane
    #pragma unroll
    for (int r = 0; r < 4; r++) {
        int i = w * 4 + r;
        float vals[5];
        float vmax = -1e30f;
        #pragma unroll
        for (int c = 0; c < 5; c++) {
            vals[c] = Ss[i * SST + lane + 32 * c];
            vmax = fmaxf(vmax, vals[c]);
        }
        #pragma unroll
        for (int off = 16; off > 0; off >>= 1)
            vmax = fmaxf(vmax, __shfl_xor_sync(0xffffffff, vmax, off));
        float sum = 0.0f;
        #pragma unroll
        for (int c = 0; c < 5; c++) {
            vals[c] = __expf(vals[c] - vmax);
            sum += vals[c];
        }
        #pragma unroll
        for (int off = 16; off > 0; off >>= 1)
            sum += __shfl_xor_sync(0xffffffff, sum, off);
        float inv = 1.0f / sum;
        #pragma unroll
        for (int c = 0; c < 5; c++)
            Ss[i * SST + lane + 32 * c] = __uint_as_float(f2tf32(vals[c] * inv));
    }
    __syncthreads();

    // O = P V. Warp w: m-tile (w&1), output n-tiles (w>>1) and (w>>1)+4
    {
        int mt = w & 1;
        int ng = w >> 1;
        float acc0[4] = {0.f, 0.f, 0.f, 0.f};
        float acc1[4] = {0.f, 0.f, 0.f, 0.f};
        int n0r = ng * 8 + gid;
        int n1r = (ng + 4) * 8 + gid;
        #pragma unroll
        for (int kk = 0; kk < 20; kk++) {
            int kb = kk * 8;
            int mr = mt * 16 + gid;
            unsigned afr[4];
            afr[0] = __float_as_uint(Ss[mr * SST + kb + tig]);
            afr[1] = __float_as_uint(Ss[(mr + 8) * SST + kb + tig]);
            afr[2] = __float_as_uint(Ss[mr * SST + kb + tig + 4]);
            afr[3] = __float_as_uint(Ss[(mr + 8) * SST + kb + tig + 4]);
            unsigned b0[2], b1[2];
            b0[0] = __float_as_uint(Vt[n0r * VTST + kb + tig]);
            b0[1] = __float_as_uint(Vt[n0r * VTST + kb + tig + 4]);
            b1[0] = __float_as_uint(Vt[n1r * VTST + kb + tig]);
            b1[1] = __float_as_uint(Vt[n1r * VTST + kb + tig + 4]);
            mma_tf32(acc0, afr, b0);
            mma_tf32(acc1, afr, b1);
        }
        float* obase = &g_att[(size_t)(b * SEQ + q0) * DIM + h * DHEAD];
        int r0 = mt * 16 + gid;
        int c0 = ng * 8 + tig * 2;
        int c1 = c0 + 32;
        *(float2*)&obase[(size_t)r0 * DIM + c0]       = make_float2(acc0[0], acc0[1]);
        *(float2*)&obase[(size_t)(r0 + 8) * DIM + c0] = make_float2(acc0[2], acc0[3]);
        *(float2*)&obase[(size_t)r0 * DIM + c1]       = make_float2(acc1[0], acc1[1]);
        *(float2*)&obase[(size_t)(r0 + 8) * DIM + c1] = make_float2(acc1[2], acc1[3]);
    }
}

// ---------------------------------------------------------------------------
// launch
// ---------------------------------------------------------------------------
extern "C" void kernel_launch(void* const* d_in, const int* in_sizes, int n_in,
                              void* d_out, int out_size) {
    const float* x      = (const float*)d_in[0];
    const float* w_norm = (const float*)d_in[1];
    const float* w_qkv  = (const float*)d_in[2];
    const float* w_out  = (const float*)d_in[3];
    float* out = (float*)d_out;

    float *p_xn, *p_qkv, *p_att;
    cudaGetSymbolAddress((void**)&p_xn,  g_xn);
    cudaGetSymbolAddress((void**)&p_qkv, g_qkv);
    cudaGetSymbolAddress((void**)&p_att, g_att);

    cudaFuncSetAttribute(gemm_tf32_kernel, cudaFuncAttributeMaxDynamicSharedMemorySize,
                         (int)GEMM_SMEM);
    size_t attn_smem = (size_t)(TQ * QST + SPAN * KSTR + DHEAD * VTST + TQ * SST)
                       * sizeof(float);
    cudaFuncSetAttribute(attn_kernel, cudaFuncAttributeMaxDynamicSharedMemorySize,
                         (int)attn_smem);

    // 1. RMSNorm
    rmsnorm_kernel<<<MROWS, 256>>>(x, w_norm);

    // 2. QKV projection (TF32 tensor cores, cp.async pipeline)
    {
        dim3 grid(N3 / GBN, MROWS / GBM);
        gemm_tf32_kernel<<<grid, 256, GEMM_SMEM>>>(p_xn, w_qkv, nullptr, p_qkv, MROWS, N3, DIM);
    }

    // 3. Banded attention (tensor cores) -> g_att[M, D]
    {
        dim3 grid(SEQ / TQ, BATCH * HEADS);
        attn_kernel<<<grid, 256, attn_smem>>>();
    }

    // 4. Output projection + residual
    {
        dim3 grid(DIM / GBN, MROWS / GBM);
        gemm_tf32_kernel<<<grid, 256, GEMM_SMEM>>>(p_att, w_out, x, out, MROWS, DIM, DIM);
    }
}